// round 6
// baseline (speedup 1.0000x reference)
#include <cuda_runtime.h>
#include <cstdint>

// YOLO-v1 style loss reduction — TMA double-buffered persistent version,
// small tiles (64 cells) x 8 blocks/SM for 8 independent pipelines per SM.
// prediction: [16384, 7, 7, 30] f32, target: [16384, 7, 7, 25] f32 -> scalar f32.

#define TPB        64
#define BLK_PER_SM 8
#define GRID       (148 * BLK_PER_SM)        // 1184
#define NCELLS     (16384 * 49)              // 802816
#define NTILES     (NCELLS / TPB)            // 12544
#define PRED_F     30
#define TARG_F     25
#define PFLT       (TPB * PRED_F)            // 1920 floats
#define TFLT       (TPB * TARG_F)            // 1600 floats
#define PBYTES     (PFLT * 4)                // 7680
#define TBYTES     (TFLT * 4)                // 6400
#define STAGE_BYTES (PBYTES + TBYTES)        // 14080
#define DYN_BYTES  (2 * STAGE_BYTES)         // 28160
#define EPSV       1e-8f

__global__ void zero_out_kernel(float* out) { *out = 0.0f; }

__device__ __forceinline__ void mbar_init(uint32_t mbar, uint32_t count) {
    asm volatile("mbarrier.init.shared.b64 [%0], %1;" :: "r"(mbar), "r"(count) : "memory");
}
__device__ __forceinline__ void mbar_expect_tx(uint32_t mbar, uint32_t bytes) {
    asm volatile("mbarrier.arrive.expect_tx.shared.b64 _, [%0], %1;"
                 :: "r"(mbar), "r"(bytes) : "memory");
}
__device__ __forceinline__ void mbar_wait(uint32_t mbar, uint32_t parity) {
    uint32_t done;
    asm volatile(
        "{\n\t.reg .pred p;\n\t"
        "mbarrier.try_wait.parity.acquire.cta.shared::cta.b64 p, [%1], %2;\n\t"
        "selp.b32 %0, 1, 0, p;\n\t}"
        : "=r"(done) : "r"(mbar), "r"(parity) : "memory");
    if (!done) {
        asm volatile(
            "{\n\t.reg .pred P1;\n\t"
            "WAIT_LOOP_%=:\n\t"
            "mbarrier.try_wait.parity.acquire.cta.shared::cta.b64 P1, [%0], %1, 0x989680;\n\t"
            "@P1 bra.uni WAIT_DONE_%=;\n\t"
            "bra.uni WAIT_LOOP_%=;\n\t"
            "WAIT_DONE_%=:\n\t}"
            :: "r"(mbar), "r"(parity) : "memory");
    }
}
__device__ __forceinline__ void bulk_cp(uint32_t dst_smem, const void* src, uint32_t bytes,
                                        uint32_t mbar) {
    asm volatile(
        "cp.async.bulk.shared::cluster.global.mbarrier::complete_tx::bytes [%0], [%1], %2, [%3];"
        :: "r"(dst_smem), "l"(src), "r"(bytes), "r"(mbar) : "memory");
}

__global__ void __launch_bounds__(TPB)
yolo_loss_kernel(const float* __restrict__ pred,
                 const float* __restrict__ targ,
                 float* __restrict__ out)
{
    extern __shared__ float dyn[];
    // layout per stage: [pred tile | targ tile], two stages.
    float* spbuf[2] = { dyn,                        dyn + (PFLT + TFLT) };
    float* stbuf[2] = { dyn + PFLT,                 dyn + (PFLT + TFLT) + PFLT };
    __shared__ __align__(8) unsigned long long mbar_s[2];
    __shared__ float wsum[TPB / 32];

    const int tid = threadIdx.x;

    uint32_t mb[2];
    mb[0] = (uint32_t)__cvta_generic_to_shared(&mbar_s[0]);
    mb[1] = (uint32_t)__cvta_generic_to_shared(&mbar_s[1]);
    uint32_t spa[2], sta[2];
    spa[0] = (uint32_t)__cvta_generic_to_shared(spbuf[0]);
    spa[1] = (uint32_t)__cvta_generic_to_shared(spbuf[1]);
    sta[0] = (uint32_t)__cvta_generic_to_shared(stbuf[0]);
    sta[1] = (uint32_t)__cvta_generic_to_shared(stbuf[1]);

    if (tid == 0) {
        mbar_init(mb[0], 1);
        mbar_init(mb[1], 1);
    }
    __syncthreads();

    // prologue: prefetch first tile into stage 0
    int tile = blockIdx.x;
    if (tid == 0) {
        mbar_expect_tx(mb[0], STAGE_BYTES);
        bulk_cp(spa[0], pred + (size_t)tile * PFLT, PBYTES, mb[0]);
        bulk_cp(sta[0], targ + (size_t)tile * TFLT, TBYTES, mb[0]);
    }

    float acc = 0.0f;
    const float invS = 1.0f / 7.0f;
    int ph0 = 0, ph1 = 0;

    for (int k = 0; tile < NTILES; tile += GRID, k++) {
        const int buf = k & 1;

        // prefetch next tile into the other stage (its readers finished at the
        // __syncthreads closing iteration k-1)
        const int nxt = tile + GRID;
        if (tid == 0 && nxt < NTILES) {
            mbar_expect_tx(mb[buf ^ 1], STAGE_BYTES);
            bulk_cp(spa[buf ^ 1], pred + (size_t)nxt * PFLT, PBYTES, mb[buf ^ 1]);
            bulk_cp(sta[buf ^ 1], targ + (size_t)nxt * TFLT, TBYTES, mb[buf ^ 1]);
        }

        // wait for current stage
        if (buf == 0) { mbar_wait(mb[0], ph0); ph0 ^= 1; }
        else          { mbar_wait(mb[1], ph1); ph1 ^= 1; }

        // ---- per-cell loss ----
        const int cell = tile * TPB + tid;
        const int rc   = cell % 49;
        const float row = (float)(rc / 7);
        const float col = (float)(rc % 7);

        const float* p  = spbuf[buf] + tid * PRED_F;
        const float* tt = stbuf[buf] + tid * TARG_F;

        const float gw = tt[2], gh = tt[3];
        const float gcx = (tt[0] + col) * invS;
        const float gcy = (tt[1] + row) * invS;
        const float gx1 = gcx - 0.5f * gw, gy1 = gcy - 0.5f * gh;
        const float gx2 = gcx + 0.5f * gw, gy2 = gcy + 0.5f * gh;
        const float ga  = fabsf(gw * gh);

        float iou0 = 0.0f, iou1 = 0.0f;
        #pragma unroll
        for (int b = 0; b < 2; b++) {
            const float* pb = p + 5 * b;
            const float w = pb[2], h = pb[3];
            const float cx = (pb[0] + col) * invS;
            const float cy = (pb[1] + row) * invS;
            const float x1 = cx - 0.5f * w, y1 = cy - 0.5f * h;
            const float x2 = cx + 0.5f * w, y2 = cy + 0.5f * h;
            const float ix = fminf(x2, gx2) - fmaxf(x1, gx1);
            const float iy = fminf(y2, gy2) - fmaxf(y1, gy1);
            const float inter = fmaxf(ix, 0.0f) * fmaxf(iy, 0.0f);
            const float pa = fabsf(w * h);
            const float v  = inter / (pa + ga - inter + EPSV);
            if (b == 0) iou0 = v; else iou1 = v;
        }
        const int bi = (iou1 > iou0) ? 1 : 0;     // argmax: first max wins
        const float* s = p + 5 * bi;

        const float gc  = tt[4];
        const bool  obj = (gc != 0.0f);

        float loss;
        if (obj) {
            const float dx = s[0] - tt[0];
            const float dy = s[1] - tt[1];
            const float center = dx * dx + dy * dy;

            const float pw = s[2], ph = s[3];
            const float sgnw = (pw > 0.0f) ? 1.0f : ((pw < 0.0f) ? -1.0f : 0.0f);
            const float sgnh = (ph > 0.0f) ? 1.0f : ((ph < 0.0f) ? -1.0f : 0.0f);
            const float swv = sgnw * sqrtf(fabsf(pw) + EPSV) - sqrtf(gw);
            const float shv = sgnh * sqrtf(fabsf(ph) + EPSV) - sqrtf(gh);
            const float dim = swv * swv + shv * shv;

            const float dc = s[4] - gc;
            float cls = 0.0f;
            #pragma unroll
            for (int c = 0; c < 20; c++) {
                const float d = p[10 + c] - tt[5 + c];
                cls += d * d;
            }
            loss = 5.0f * (center + dim) + dc * dc + cls;
        } else {
            const float d0 = p[4] - gc;
            const float d1 = p[9] - gc;
            loss = 0.5f * (d0 * d0 + d1 * d1);
        }
        acc += loss;

        __syncthreads();   // all readers done with buf before it is refilled (k+2)
    }

    // ---- block reduction (2 warps) ----
    #pragma unroll
    for (int o = 16; o > 0; o >>= 1)
        acc += __shfl_down_sync(0xffffffffu, acc, o);
    if ((tid & 31) == 0) wsum[tid >> 5] = acc;
    __syncthreads();
    if (tid == 0) {
        atomicAdd(out, wsum[0] + wsum[1]);
    }
}

extern "C" void kernel_launch(void* const* d_in, const int* in_sizes, int n_in,
                              void* d_out, int out_size)
{
    const float* pred = (const float*)d_in[0];
    const float* targ = (const float*)d_in[1];
    float* out = (float*)d_out;

    cudaFuncSetAttribute(yolo_loss_kernel,
                         cudaFuncAttributeMaxDynamicSharedMemorySize,
                         DYN_BYTES);

    zero_out_kernel<<<1, 1>>>(out);
    yolo_loss_kernel<<<GRID, TPB, DYN_BYTES>>>(pred, targ, out);
}

// round 7
// speedup vs baseline: 1.0135x; 1.0135x over previous
#include <cuda_runtime.h>
#include <cstdint>

// YOLO-v1 style loss reduction — warp-autonomous TMA pipelines.
// prediction: [16384, 7, 7, 30] f32, target: [16384, 7, 7, 25] f32 -> scalar f32.
//
// Each WARP owns an independent double-buffered cp.async.bulk stream of
// 32-cell sub-tiles with private mbarriers. No __syncthreads in the main
// loop; no cross-warp coupling. 4 blocks/SM x 4 warps = 16 decoupled
// pipelines per SM.

#define TPB         128
#define WARPS       (TPB / 32)               // 4
#define BLK_PER_SM  4
#define GRID        (148 * BLK_PER_SM)       // 592
#define NSTREAMS    (GRID * WARPS)           // 2368 warp streams
#define NCELLS      (16384 * 49)             // 802816
#define NSUB        (NCELLS / 32)            // 25088 sub-tiles of 32 cells
#define PRED_F      30
#define TARG_F      25
#define PFLT        (32 * PRED_F)            // 960 floats / sub-tile
#define TFLT        (32 * TARG_F)            // 800 floats / sub-tile
#define PBYTES      (PFLT * 4)               // 3840
#define TBYTES      (TFLT * 4)               // 3200
#define STAGE_FLT   (PFLT + TFLT)            // 1760 floats = 7040 B
#define STAGE_BYTES (STAGE_FLT * 4)
#define DYN_BYTES   (WARPS * 2 * STAGE_BYTES)  // 56320
#define EPSV        1e-8f

__global__ void zero_out_kernel(float* out) { *out = 0.0f; }

__device__ __forceinline__ void mbar_init(uint32_t mbar, uint32_t count) {
    asm volatile("mbarrier.init.shared.b64 [%0], %1;" :: "r"(mbar), "r"(count) : "memory");
}
__device__ __forceinline__ void mbar_expect_tx(uint32_t mbar, uint32_t bytes) {
    asm volatile("mbarrier.arrive.expect_tx.shared.b64 _, [%0], %1;"
                 :: "r"(mbar), "r"(bytes) : "memory");
}
__device__ __forceinline__ void mbar_wait(uint32_t mbar, uint32_t parity) {
    uint32_t done;
    asm volatile(
        "{\n\t.reg .pred p;\n\t"
        "mbarrier.try_wait.parity.acquire.cta.shared::cta.b64 p, [%1], %2;\n\t"
        "selp.b32 %0, 1, 0, p;\n\t}"
        : "=r"(done) : "r"(mbar), "r"(parity) : "memory");
    if (!done) {
        asm volatile(
            "{\n\t.reg .pred P1;\n\t"
            "WAIT_LOOP_%=:\n\t"
            "mbarrier.try_wait.parity.acquire.cta.shared::cta.b64 P1, [%0], %1, 0x989680;\n\t"
            "@P1 bra.uni WAIT_DONE_%=;\n\t"
            "bra.uni WAIT_LOOP_%=;\n\t"
            "WAIT_DONE_%=:\n\t}"
            :: "r"(mbar), "r"(parity) : "memory");
    }
}
__device__ __forceinline__ void bulk_cp(uint32_t dst_smem, const void* src, uint32_t bytes,
                                        uint32_t mbar) {
    asm volatile(
        "cp.async.bulk.shared::cluster.global.mbarrier::complete_tx::bytes [%0], [%1], %2, [%3];"
        :: "r"(dst_smem), "l"(src), "r"(bytes), "r"(mbar) : "memory");
}

__global__ void __launch_bounds__(TPB)
yolo_loss_kernel(const float* __restrict__ pred,
                 const float* __restrict__ targ,
                 float* __restrict__ out)
{
    extern __shared__ float dyn[];
    __shared__ __align__(8) unsigned long long mbar_s[WARPS * 2];

    const int tid  = threadIdx.x;
    const int wid  = tid >> 5;
    const int lane = tid & 31;

    // per-warp stage buffers: [warp][stage] -> pred(960f) | targ(800f)
    float* stage_base = dyn + wid * 2 * STAGE_FLT;
    float* sp[2] = { stage_base,                       stage_base + STAGE_FLT };
    float* st[2] = { stage_base + PFLT,                stage_base + STAGE_FLT + PFLT };

    uint32_t mb[2];
    mb[0] = (uint32_t)__cvta_generic_to_shared(&mbar_s[wid * 2 + 0]);
    mb[1] = (uint32_t)__cvta_generic_to_shared(&mbar_s[wid * 2 + 1]);
    uint32_t spa[2];
    spa[0] = (uint32_t)__cvta_generic_to_shared(sp[0]);
    spa[1] = (uint32_t)__cvta_generic_to_shared(sp[1]);
    uint32_t sta[2];
    sta[0] = (uint32_t)__cvta_generic_to_shared(st[0]);
    sta[1] = (uint32_t)__cvta_generic_to_shared(st[1]);

    if (lane == 0) {
        mbar_init(mb[0], 1);
        mbar_init(mb[1], 1);
    }
    __syncthreads();   // only once: mbarriers visible (same-warp use, but cheap)

    // this warp's stream of sub-tiles: stream, stream+NSTREAMS, ...
    const int stream = blockIdx.x * WARPS + wid;

    // prologue: prefetch first sub-tile into stage 0
    int sub = stream;
    if (lane == 0 && sub < NSUB) {
        mbar_expect_tx(mb[0], STAGE_BYTES);
        bulk_cp(spa[0], pred + (size_t)sub * PFLT, PBYTES, mb[0]);
        bulk_cp(sta[0], targ + (size_t)sub * TFLT, TBYTES, mb[0]);
    }

    float acc = 0.0f;
    const float invS = 1.0f / 7.0f;
    int ph[2] = { 0, 0 };

    for (int k = 0; sub < NSUB; sub += NSTREAMS, k++) {
        const int buf = k & 1;

        // prefetch next sub-tile into the other stage
        const int nxt = sub + NSTREAMS;
        if (lane == 0 && nxt < NSUB) {
            mbar_expect_tx(mb[buf ^ 1], STAGE_BYTES);
            bulk_cp(spa[buf ^ 1], pred + (size_t)nxt * PFLT, PBYTES, mb[buf ^ 1]);
            bulk_cp(sta[buf ^ 1], targ + (size_t)nxt * TFLT, TBYTES, mb[buf ^ 1]);
        }

        // wait for current stage (warp-private)
        mbar_wait(mb[buf], ph[buf]);
        ph[buf] ^= 1;

        // ---- per-cell loss: cell = sub*32 + lane ----
        const int cell = sub * 32 + lane;
        const int rc   = cell % 49;
        const float row = (float)(rc / 7);
        const float col = (float)(rc % 7);

        const float* p  = sp[buf] + lane * PRED_F;
        const float* tt = st[buf] + lane * TARG_F;

        const float gw = tt[2], gh = tt[3];
        const float gcx = (tt[0] + col) * invS;
        const float gcy = (tt[1] + row) * invS;
        const float gx1 = gcx - 0.5f * gw, gy1 = gcy - 0.5f * gh;
        const float gx2 = gcx + 0.5f * gw, gy2 = gcy + 0.5f * gh;
        const float ga  = fabsf(gw * gh);

        float iou0 = 0.0f, iou1 = 0.0f;
        #pragma unroll
        for (int b = 0; b < 2; b++) {
            const float* pb = p + 5 * b;
            const float w = pb[2], h = pb[3];
            const float cx = (pb[0] + col) * invS;
            const float cy = (pb[1] + row) * invS;
            const float x1 = cx - 0.5f * w, y1 = cy - 0.5f * h;
            const float x2 = cx + 0.5f * w, y2 = cy + 0.5f * h;
            const float ix = fminf(x2, gx2) - fmaxf(x1, gx1);
            const float iy = fminf(y2, gy2) - fmaxf(y1, gy1);
            const float inter = fmaxf(ix, 0.0f) * fmaxf(iy, 0.0f);
            const float pa = fabsf(w * h);
            const float v  = inter / (pa + ga - inter + EPSV);
            if (b == 0) iou0 = v; else iou1 = v;
        }
        const int bi = (iou1 > iou0) ? 1 : 0;     // argmax: first max wins
        const float* s = p + 5 * bi;

        const float gc  = tt[4];
        const bool  obj = (gc != 0.0f);

        float loss;
        if (obj) {
            const float dx = s[0] - tt[0];
            const float dy = s[1] - tt[1];
            const float center = dx * dx + dy * dy;

            const float pw = s[2], phh = s[3];
            const float sgnw = (pw > 0.0f) ? 1.0f : ((pw < 0.0f) ? -1.0f : 0.0f);
            const float sgnh = (phh > 0.0f) ? 1.0f : ((phh < 0.0f) ? -1.0f : 0.0f);
            const float swv = sgnw * sqrtf(fabsf(pw) + EPSV) - sqrtf(gw);
            const float shv = sgnh * sqrtf(fabsf(phh) + EPSV) - sqrtf(gh);
            const float dim = swv * swv + shv * shv;

            const float dc = s[4] - gc;
            float cls = 0.0f;
            #pragma unroll
            for (int c = 0; c < 20; c++) {
                const float d = p[10 + c] - tt[5 + c];
                cls += d * d;
            }
            loss = 5.0f * (center + dim) + dc * dc + cls;
        } else {
            const float d0 = p[4] - gc;
            const float d1 = p[9] - gc;
            loss = 0.5f * (d0 * d0 + d1 * d1);
        }
        acc += loss;

        __syncwarp();   // all lanes done reading buf before lane 0 refills it (k+2)
    }

    // ---- warp reduction + one atomic per warp ----
    #pragma unroll
    for (int o = 16; o > 0; o >>= 1)
        acc += __shfl_down_sync(0xffffffffu, acc, o);
    if (lane == 0)
        atomicAdd(out, acc);
}

extern "C" void kernel_launch(void* const* d_in, const int* in_sizes, int n_in,
                              void* d_out, int out_size)
{
    const float* pred = (const float*)d_in[0];
    const float* targ = (const float*)d_in[1];
    float* out = (float*)d_out;

    cudaFuncSetAttribute(yolo_loss_kernel,
                         cudaFuncAttributeMaxDynamicSharedMemorySize,
                         DYN_BYTES);

    zero_out_kernel<<<1, 1>>>(out);
    yolo_loss_kernel<<<GRID, TPB, DYN_BYTES>>>(pred, targ, out);
}

// round 9
// speedup vs baseline: 1.0518x; 1.0378x over previous
#include <cuda_runtime.h>

// YOLO-v1 style loss reduction — persistent one-wave grid + cp.async
// double-buffered staging (the best-measured R4 engine, de-quantized).
// prediction: [16384, 7, 7, 30] f32, target: [16384, 7, 7, 25] f32 -> scalar f32.

#define TPB        128
#define GRID       592                       // 148 SMs x 4 blocks (one exact wave)
#define NCELLS     (16384 * 49)              // 802816
#define NTILES     (NCELLS / TPB)            // 6272
#define PRED_F     30
#define TARG_F     25
#define PV4        (TPB * PRED_F / 4)        // 960 float4 per pred tile
#define TV4        (TPB * TARG_F / 4)        // 800 float4 per targ tile
#define PFLT       (TPB * PRED_F)            // 3840 floats
#define TFLT       (TPB * TARG_F)            // 3200 floats
#define DYN_BYTES  ((2 * PFLT + 2 * TFLT) * 4)   // 56320
#define EPSV       1e-8f

__global__ void zero_out_kernel(float* out) { *out = 0.0f; }

__device__ __forceinline__ void cp16(unsigned smem_addr, const float4* g) {
    asm volatile("cp.async.cg.shared.global [%0], [%1], 16;\n"
                 :: "r"(smem_addr), "l"(g));
}

__device__ __forceinline__ void prefetch_tile(int tile,
                                              unsigned spa, unsigned sta,
                                              const float4* gp_base,
                                              const float4* gt_base,
                                              int tid)
{
    const float4* gp = gp_base + (size_t)tile * PV4;
    const float4* gt = gt_base + (size_t)tile * TV4;
    #pragma unroll
    for (int i = tid; i < PV4; i += TPB) cp16(spa + i * 16u, gp + i);
    #pragma unroll
    for (int i = tid; i < TV4; i += TPB) cp16(sta + i * 16u, gt + i);
    asm volatile("cp.async.commit_group;\n");
}

__global__ void __launch_bounds__(TPB)
yolo_loss_kernel(const float* __restrict__ pred,
                 const float* __restrict__ targ,
                 float* __restrict__ out)
{
    extern __shared__ float dyn[];
    // layout: sp0 | sp1 | st0 | st1
    float* spbuf[2] = { dyn,              dyn + PFLT };
    float* stbuf[2] = { dyn + 2 * PFLT,   dyn + 2 * PFLT + TFLT };
    __shared__ float wsum[TPB / 32];

    const int tid = threadIdx.x;
    const float4* gp_base = (const float4*)pred;
    const float4* gt_base = (const float4*)targ;

    unsigned spa[2], sta[2];
    spa[0] = (unsigned)__cvta_generic_to_shared(spbuf[0]);
    spa[1] = (unsigned)__cvta_generic_to_shared(spbuf[1]);
    sta[0] = (unsigned)__cvta_generic_to_shared(stbuf[0]);
    sta[1] = (unsigned)__cvta_generic_to_shared(stbuf[1]);

    // prologue: prefetch first tile into stage 0
    int tile = blockIdx.x;
    prefetch_tile(tile, spa[0], sta[0], gp_base, gt_base, tid);

    float acc = 0.0f;
    const float invS = 1.0f / 7.0f;

    for (int k = 0; tile < NTILES; tile += GRID, k++) {
        const int buf = k & 1;
        const int nxt = tile + GRID;
        if (nxt < NTILES) {
            prefetch_tile(nxt, spa[buf ^ 1], sta[buf ^ 1], gp_base, gt_base, tid);
            asm volatile("cp.async.wait_group 1;\n");
        } else {
            asm volatile("cp.async.wait_group 0;\n");
        }
        __syncthreads();

        // ---- per-cell loss for this tile ----
        const int cell = tile * TPB + tid;
        const int rc   = cell % 49;
        const float row = (float)(rc / 7);
        const float col = (float)(rc % 7);

        const float* p  = spbuf[buf] + tid * PRED_F;
        const float* tt = stbuf[buf] + tid * TARG_F;

        const float gw = tt[2], gh = tt[3];
        const float gcx = (tt[0] + col) * invS;
        const float gcy = (tt[1] + row) * invS;
        const float gx1 = gcx - 0.5f * gw, gy1 = gcy - 0.5f * gh;
        const float gx2 = gcx + 0.5f * gw, gy2 = gcy + 0.5f * gh;
        const float ga  = fabsf(gw * gh);

        float iou0 = 0.0f, iou1 = 0.0f;
        #pragma unroll
        for (int b = 0; b < 2; b++) {
            const float* pb = p + 5 * b;
            const float w = pb[2], h = pb[3];
            const float cx = (pb[0] + col) * invS;
            const float cy = (pb[1] + row) * invS;
            const float x1 = cx - 0.5f * w, y1 = cy - 0.5f * h;
            const float x2 = cx + 0.5f * w, y2 = cy + 0.5f * h;
            const float ix = fminf(x2, gx2) - fmaxf(x1, gx1);
            const float iy = fminf(y2, gy2) - fmaxf(y1, gy1);
            const float inter = fmaxf(ix, 0.0f) * fmaxf(iy, 0.0f);
            const float pa = fabsf(w * h);
            const float v  = inter / (pa + ga - inter + EPSV);
            if (b == 0) iou0 = v; else iou1 = v;
        }
        const int bi = (iou1 > iou0) ? 1 : 0;     // argmax: first max wins
        const float* s = p + 5 * bi;

        const float gc  = tt[4];
        const bool  obj = (gc != 0.0f);

        float loss;
        if (obj) {
            const float dx = s[0] - tt[0];
            const float dy = s[1] - tt[1];
            const float center = dx * dx + dy * dy;

            const float pw = s[2], ph = s[3];
            const float sgnw = (pw > 0.0f) ? 1.0f : ((pw < 0.0f) ? -1.0f : 0.0f);
            const float sgnh = (ph > 0.0f) ? 1.0f : ((ph < 0.0f) ? -1.0f : 0.0f);
            const float swv = sgnw * sqrtf(fabsf(pw) + EPSV) - sqrtf(gw);
            const float shv = sgnh * sqrtf(fabsf(ph) + EPSV) - sqrtf(gh);
            const float dim = swv * swv + shv * shv;

            const float dc = s[4] - gc;
            float cls = 0.0f;
            #pragma unroll
            for (int c = 0; c < 20; c++) {
                const float d = p[10 + c] - tt[5 + c];
                cls += d * d;
            }
            loss = 5.0f * (center + dim) + dc * dc + cls;
        } else {
            const float d0 = p[4] - gc;
            const float d1 = p[9] - gc;
            loss = 0.5f * (d0 * d0 + d1 * d1);
        }
        acc += loss;

        __syncthreads();   // all readers done with buf before it is refilled (k+2)
    }

    // ---- block reduction ----
    #pragma unroll
    for (int o = 16; o > 0; o >>= 1)
        acc += __shfl_down_sync(0xffffffffu, acc, o);
    if ((tid & 31) == 0) wsum[tid >> 5] = acc;
    __syncthreads();
    if (tid < (TPB / 32)) {
        float v = wsum[tid];
        #pragma unroll
        for (int o = (TPB / 64); o > 0; o >>= 1)
            v += __shfl_down_sync(0x0000000fu, v, o);
        if (tid == 0) atomicAdd(out, v);
    }
}

extern "C" void kernel_launch(void* const* d_in, const int* in_sizes, int n_in,
                              void* d_out, int out_size)
{
    const float* pred = (const float*)d_in[0];
    const float* targ = (const float*)d_in[1];
    float* out = (float*)d_out;

    cudaFuncSetAttribute(yolo_loss_kernel,
                         cudaFuncAttributeMaxDynamicSharedMemorySize,
                         DYN_BYTES);

    zero_out_kernel<<<1, 1>>>(out);
    yolo_loss_kernel<<<GRID, TPB, DYN_BYTES>>>(pred, targ, out);
}